// round 7
// baseline (speedup 1.0000x reference)
#include <cuda_runtime.h>
#include <cstdint>
#include <math.h>

#define TS 63
#define B 32
#define S 256
#define H 512
#define V 32000
#define G4 2048
typedef unsigned long long ull;

// ------------------------- device scratch -----------------------------------
__device__ float g_h[2][B*H];
__device__ float g_c[2][B*H];
__device__ float g_emb[TS][B*H];
__device__ float g_dec[B*H];        // input_feed / dec_out (b-major)
__device__ float g_decT[H*B];       // dec_out transposed [k][b]
__device__ float g_ctx[B*H];
__device__ float g_part0[3][G4*B];
__device__ float g_part1[2][G4*B];
__device__ float g_WaT[H*H];
__device__ float g_sumZ[TS*B];

// ------------------------- f32x2 / cp.async helpers --------------------------
__device__ __forceinline__ ull fma2(ull a, ull b, ull c) {
    ull d; asm("fma.rn.f32x2 %0, %1, %2, %3;" : "=l"(d) : "l"(a), "l"(b), "l"(c));
    return d;
}
__device__ __forceinline__ ull dup2(float x) {
    ull d; asm("mov.b64 %0, {%1, %1};" : "=l"(d) : "f"(x));
    return d;
}
__device__ __forceinline__ void unpack2(ull v, float& lo, float& hi) {
    asm("mov.b64 {%0, %1}, %2;" : "=f"(lo), "=f"(hi) : "l"(v));
}
__device__ __forceinline__ void cp8(uint32_t dst, const void* src) {
    asm volatile("cp.async.ca.shared.global [%0], [%1], 8;" :: "r"(dst), "l"(src));
}
__device__ __forceinline__ void cp_commit() {
    asm volatile("cp.async.commit_group;");
}
template <int N>
__device__ __forceinline__ void cp_wait() {
    asm volatile("cp.async.wait_group %0;" :: "n"(N));
}

// ------------------------- shared-memory union --------------------------------
struct GenSmem {
    float2 Ws[2][128*16];   // 32768 B  [buf][n*16 + ((k2 ^ (n>>2)) & 15)]
    float2 Xs[2][32*17];    //  8704 B  [buf][k*17 + bpair]
    float  red[32*33];      //  4224 B
};
union StepSmem {
    float   gemv[8][33*32]; // 33792 B
    GenSmem gen;            // 45696 B
};

// ------------------------- warp GEMV helpers (LSTM path) ---------------------
__device__ __forceinline__ void warp_gemv_acc(const float* __restrict__ Wrow,
                                              const float* __restrict__ X,
                                              float acc[B]) {
    const int lane = threadIdx.x & 31;
#pragma unroll
    for (int kk = 0; kk < 4; kk++) {
        const int k = kk*128 + lane*4;
        const float4 w = *reinterpret_cast<const float4*>(Wrow + k);
#pragma unroll
        for (int b = 0; b < B; b++) {
            const float4 x = *reinterpret_cast<const float4*>(X + b*H + k);
            acc[b] += w.x*x.x + w.y*x.y + w.z*x.z + w.w*x.w;
        }
    }
}
__device__ __forceinline__ float warp_reduce_b(float acc[B], float* sm) {
    const int lane = threadIdx.x & 31;
#pragma unroll
    for (int b = 0; b < B; b++) sm[b*33 + lane] = acc[b];
    __syncwarp();
    float s = 0.f;
#pragma unroll
    for (int j = 0; j < 32; j++) s += sm[lane*33 + j];
    return s;
}

__device__ __forceinline__ float sigm(float x) { return 1.f/(1.f+expf(-x)); }

// ------------------------- generator tile (256 threads) ----------------------
__device__ void gen_tile(int tileIdx, int tGen,
                         const float* __restrict__ Wgen,
                         const float* __restrict__ bgen,
                         float* __restrict__ out, GenSmem& g) {
    const int tid = threadIdx.x;
    const int bg = tid & 7, ng = tid >> 3;            // 32 ngroups x 8 bgroups
    const int nt = tileIdx * 128;

    uint32_t wsB[2], xsB[2];
    wsB[0] = (uint32_t)__cvta_generic_to_shared(&g.Ws[0][0]);
    wsB[1] = (uint32_t)__cvta_generic_to_shared(&g.Ws[1][0]);
    xsB[0] = (uint32_t)__cvta_generic_to_shared(&g.Xs[0][0]);
    xsB[1] = (uint32_t)__cvta_generic_to_shared(&g.Xs[1][0]);

    const float2* wsrc_base = reinterpret_cast<const float2*>(Wgen) + (size_t)nt*256;
    const float2* xsrc_base = reinterpret_cast<const float2*>(g_decT);

    auto prefetch = [&](int c, int buf) {
        const int row = tid >> 1, g0 = (tid & 1) * 8;
        const float2* src = wsrc_base + (size_t)row*256 + c*16 + g0;
        const int sw = row >> 2;
#pragma unroll
        for (int j = 0; j < 8; j++)
            cp8(wsB[buf] + (uint32_t)(row*16 + (((g0 + j) ^ sw) & 15))*8, src + j);
#pragma unroll
        for (int j = 0; j < 2; j++) {
            int idx = tid*2 + j;                      // 0..511
            int k = idx >> 4, bp = idx & 15;
            cp8(xsB[buf] + (uint32_t)(k*17 + bp)*8, xsrc_base + (size_t)(c*32 + k)*16 + bp);
        }
        cp_commit();
    };

    ull acc[4][2] = {};                               // [n_i][b-pair(b01,b23)]

    prefetch(0, 0);
    prefetch(1, 1);

    for (int c = 0; c < 16; c++) {
        if (c < 14) cp_wait<1>(); else cp_wait<0>();
        __syncthreads();
        const int buf = c & 1;
        const float2* W = &g.Ws[buf][0];
        const float2* X = &g.Xs[buf][0];
#pragma unroll 4
        for (int k2 = 0; k2 < 16; k2++) {
            const int k0 = 2*k2, k1 = 2*k2 + 1;
            ull xA0 = *reinterpret_cast<const ull*>(X + k0*17 + bg*2);
            ull xA1 = *reinterpret_cast<const ull*>(X + k0*17 + bg*2 + 1);
            ull xB0 = *reinterpret_cast<const ull*>(X + k1*17 + bg*2);
            ull xB1 = *reinterpret_cast<const ull*>(X + k1*17 + bg*2 + 1);
            const int sw = (k2 ^ ng) & 15;
#pragma unroll
            for (int i = 0; i < 4; i++) {
                float2 w = W[(ng*4 + i)*16 + sw];
                ull wA = dup2(w.x), wB = dup2(w.y);
                acc[i][0] = fma2(wA, xA0, acc[i][0]);
                acc[i][1] = fma2(wA, xA1, acc[i][1]);
                acc[i][0] = fma2(wB, xB0, acc[i][0]);
                acc[i][1] = fma2(wB, xB1, acc[i][1]);
            }
        }
        __syncthreads();
        if (c + 2 < 16) prefetch(c + 2, buf);
    }

    // ---- epilogue: bias, store logits, fused exp-sum ----
    float sv[4][4];
#pragma unroll
    for (int i = 0; i < 4; i++) {
        float bb = bgen[nt + ng*4 + i];
        unpack2(acc[i][0], sv[i][0], sv[i][1]);
        unpack2(acc[i][1], sv[i][2], sv[i][3]);
        sv[i][0]+=bb; sv[i][1]+=bb; sv[i][2]+=bb; sv[i][3]+=bb;
    }
#pragma unroll
    for (int jb = 0; jb < 4; jb++) {
        int b = bg*4 + jb;
        float* orow = out + ((size_t)(tGen*B + b))*V + nt + ng*4;
        *reinterpret_cast<float4*>(orow) =
            make_float4(sv[0][jb], sv[1][jb], sv[2][jb], sv[3][jb]);
        float es = expf(sv[0][jb]) + expf(sv[1][jb]) + expf(sv[2][jb]) + expf(sv[3][jb]);
        g.red[b*33 + ng] = es;
    }
    __syncthreads();
    if (tid < 32) {
        float ssum = 0.f;
#pragma unroll
        for (int j = 0; j < 32; j++) ssum += g.red[tid*33 + j];
        atomicAdd(&g_sumZ[tGen*B + tid], ssum);
    }
}

// ------------------------- kernels ------------------------------------------
__global__ void __launch_bounds__(256) k_init(const float* __restrict__ eh,
                                              const float* __restrict__ ec,
                                              const float* __restrict__ Wa) {
    int idx = blockIdx.x*256 + threadIdx.x;          // grid covers H*H
    if (idx < 2*B*H) { (&g_h[0][0])[idx] = eh[idx]; (&g_c[0][0])[idx] = ec[idx]; }
    if (idx < B*H)   { g_dec[idx] = 0.f; g_decT[idx] = 0.f; }
    if (idx < TS*B)  g_sumZ[idx] = 0.f;
    if (idx < H*H)   { int h = idx / H; int k = idx - h*H; g_WaT[k*H + h] = Wa[idx]; }
}

__global__ void __launch_bounds__(256) k_embed(const int* __restrict__ tgt,
                                               const float* __restrict__ et) {
    int idx = blockIdx.x*256 + threadIdx.x;          // < TS*B*H
    int e = idx & (H - 1);
    int r = idx >> 9;                                 // t*B + b
    int tok = tgt[r];
    (&g_emb[0][0])[idx] = et[(size_t)tok*H + e];
}

// Merged: generator for step tGen (blocks 0..genBlocks-1) + 4 gate GEMVs for
// step t (remaining blocks). The two halves are data-independent.
__global__ void __launch_bounds__(256) k_step(const float* __restrict__ Wx0,
                                              const float* __restrict__ Wh0,
                                              const float* __restrict__ Wh1,
                                              const float* __restrict__ Wgen,
                                              const float* __restrict__ bgen,
                                              float* __restrict__ out,
                                              int t, int tGen, int genBlocks) {
    __shared__ StepSmem u;
    if ((int)blockIdx.x < genBlocks) {
        if (tGen < 0) return;
        gen_tile(blockIdx.x, tGen, Wgen, bgen, out, u.gen);
        return;
    }
    const int blk = blockIdx.x - genBlocks;           // 0..1023
    const int p = blk >> 8, nb = blk & 255;
    const int warp = threadIdx.x >> 5, lane = threadIdx.x & 31;
    const int n = nb*8 + warp;                        // 0..2047
    const float* Wrow; const float* X; float* dst;
    if (p == 0)      { Wrow = Wx0 + (size_t)n*1024;        X = g_emb[t]; dst = &g_part0[0][0]; }
    else if (p == 1) { Wrow = Wx0 + (size_t)n*1024 + 512;  X = g_dec;    dst = &g_part0[1][0]; }
    else if (p == 2) { Wrow = Wh0 + (size_t)n*512;         X = g_h[0];   dst = &g_part0[2][0]; }
    else             { Wrow = Wh1 + (size_t)n*512;         X = g_h[1];   dst = &g_part1[1][0]; }
    float acc[B] = {};
    warp_gemv_acc(Wrow, X, acc);
    float s = warp_reduce_b(acc, u.gemv[warp]);
    dst[n*B + lane] = s;
}

// Wx1 x h0 (needs act0 output) -> part1[0]
__global__ void __launch_bounds__(256) k_g1p0(const float* __restrict__ Wx1) {
    __shared__ float sm[8][33*32];
    const int warp = threadIdx.x >> 5, lane = threadIdx.x & 31;
    const int n = blockIdx.x*8 + warp;
    float acc[B] = {};
    warp_gemv_acc(Wx1 + (size_t)n*512, g_h[0], acc);
    float s = warp_reduce_b(acc, sm[warp]);
    g_part1[0][n*B + lane] = s;
}

// Layer-0 activation (3 partials)
__global__ void __launch_bounds__(256) k_act0(const float* __restrict__ bias) {
    int idx = blockIdx.x*256 + threadIdx.x;           // < B*H
    int b = idx & 31, j = idx >> 5;
    float gi = bias[j], gf = bias[512+j], gg = bias[1024+j], go = bias[1536+j];
#pragma unroll
    for (int p = 0; p < 3; p++) {
        const float* pp = &g_part0[p][0];
        gi += pp[(j       )*B + b];
        gf += pp[(512 + j )*B + b];
        gg += pp[(1024 + j)*B + b];
        go += pp[(1536 + j)*B + b];
    }
    float c  = g_c[0][b*H + j];
    float cn = sigm(gf)*c + sigm(gi)*tanhf(gg);
    g_c[0][b*H + j] = cn;
    g_h[0][b*H + j] = sigm(go)*tanhf(cn);
}

// Fused: layer-1 activation + q projection + attention + context. One block per batch.
__global__ void __launch_bounds__(256) k_attn(const float* __restrict__ mb,
                                              const int* __restrict__ mlen,
                                              const float* __restrict__ b1v,
                                              float* __restrict__ attn_out, int t) {
    __shared__ float sh1[H];
    __shared__ float sq[H];
    __shared__ float al[S];
    __shared__ float red[256];
    const int b = blockIdx.x;
    const int tid = threadIdx.x, warp = tid >> 5, lane = tid & 31;
    const int len = mlen[b];

    // ---- act1 for this batch ----
    for (int j = tid; j < H; j += 256) {
        float gi = b1v[j], gf = b1v[512+j], gg = b1v[1024+j], go = b1v[1536+j];
#pragma unroll
        for (int p = 0; p < 2; p++) {
            const float* pp = &g_part1[p][0];
            gi += pp[(j       )*B + b];
            gf += pp[(512 + j )*B + b];
            gg += pp[(1024 + j)*B + b];
            go += pp[(1536 + j)*B + b];
        }
        float c  = g_c[1][b*H + j];
        float cn = sigm(gf)*c + sigm(gi)*tanhf(gg);
        g_c[1][b*H + j] = cn;
        float hn = sigm(go)*tanhf(cn);
        g_h[1][b*H + j] = hn;
        sh1[j] = hn;
    }
    __syncthreads();

    // ---- q[n] = sum_k h1[k] * Wa[k][n] ----
    for (int n = tid; n < H; n += 256) {
        const float4* wr = reinterpret_cast<const float4*>(g_WaT + (size_t)n*H);
        float a = 0.f;
#pragma unroll 8
        for (int k4 = 0; k4 < H/4; k4++) {
            float4 w = wr[k4];
            float4 hx = *reinterpret_cast<const float4*>(sh1 + k4*4);
            a += w.x*hx.x + w.y*hx.y + w.z*hx.z + w.w*hx.w;
        }
        sq[n] = a;
    }
    __syncthreads();

    // ---- alignment scores ----
    for (int s0 = warp; s0 < S; s0 += 8) {
        const float* m = mb + ((size_t)s0*B + b)*H;
        float a = 0.f;
#pragma unroll
        for (int kk = 0; kk < 4; kk++) {
            int k = kk*128 + lane*4;
            float4 mv = *reinterpret_cast<const float4*>(m + k);
            float4 qv = *reinterpret_cast<const float4*>(sq + k);
            a += mv.x*qv.x + mv.y*qv.y + mv.z*qv.z + mv.w*qv.w;
        }
#pragma unroll
        for (int off = 16; off; off >>= 1) a += __shfl_xor_sync(0xffffffffu, a, off);
        if (lane == 0) al[s0] = (s0 < len) ? a : -1.0e9f;
    }
    __syncthreads();

    // ---- softmax over S=256 ----
    float v = al[tid];
    red[tid] = v; __syncthreads();
    for (int o = 128; o; o >>= 1) { if (tid < o) red[tid] = fmaxf(red[tid], red[tid+o]); __syncthreads(); }
    float vmax = red[0];
    __syncthreads();
    float e = expf(v - vmax);
    red[tid] = e; __syncthreads();
    for (int o = 128; o; o >>= 1) { if (tid < o) red[tid] += red[tid+o]; __syncthreads(); }
    float p = e / red[0];
    al[tid] = p;
    attn_out[((size_t)t*B + b)*S + tid] = p;
    __syncthreads();

    // ---- context ----
    for (int k = tid; k < H; k += 256) {
        float acc = 0.f;
#pragma unroll 4
        for (int s = 0; s < S; s++) acc += al[s] * mb[((size_t)s*B + b)*H + k];
        g_ctx[b*H + k] = acc;
    }
}

__global__ void __launch_bounds__(256) k_wc(const float* __restrict__ Wc) {
    __shared__ float sm[8][33*32];
    const int warp = threadIdx.x >> 5, lane = threadIdx.x & 31;
    const int n = blockIdx.x*8 + warp;                // 0..511
    float acc[B] = {};
    warp_gemv_acc(Wc + (size_t)n*1024,       g_ctx,  acc);
    warp_gemv_acc(Wc + (size_t)n*1024 + 512, g_h[1], acc);
    float s = warp_reduce_b(acc, sm[warp]);
    float d = tanhf(s);
    g_dec [lane*H + n] = d;
    g_decT[n*B + lane] = d;                           // transposed copy for gen
}

// one pass at the end over all timesteps
__global__ void __launch_bounds__(256) k_lsm(float* __restrict__ out) {
    __shared__ float lz;
    const int t = blockIdx.z, b = blockIdx.y;
    if (threadIdx.x == 0) lz = logf(g_sumZ[t*B + b]);
    __syncthreads();
    int v = blockIdx.x*256 + threadIdx.x;
    out[((size_t)(t*B + b))*V + v] -= lz;
}

// ------------------------- launch -------------------------------------------
extern "C" void kernel_launch(void* const* d_in, const int* in_sizes, int n_in,
                              void* d_out, int out_size) {
    const int*   tgt   = (const int*)  d_in[0];
    const float* mb    = (const float*)d_in[1];
    const int*   mlen  = (const int*)  d_in[2];
    const float* enc_h = (const float*)d_in[3];
    const float* enc_c = (const float*)d_in[4];
    const float* emb   = (const float*)d_in[5];
    const float* Wx0   = (const float*)d_in[6];
    const float* Wh0   = (const float*)d_in[7];
    const float* b0    = (const float*)d_in[8];
    const float* Wx1   = (const float*)d_in[9];
    const float* Wh1   = (const float*)d_in[10];
    const float* b1    = (const float*)d_in[11];
    const float* Wa    = (const float*)d_in[12];
    const float* Wc    = (const float*)d_in[13];
    const float* Wgen  = (const float*)d_in[14];
    const float* bgen  = (const float*)d_in[15];

    float* out      = (float*)d_out;
    float* attn_out = out + (size_t)TS*B*V;

    const int GEN_BLOCKS = V/128;                     // 250

    k_init <<<(H*H + 255)/256, 256>>>(enc_h, enc_c, Wa);
    k_embed<<<(TS*B*H)/256, 256>>>(tgt, emb);

    for (int t = 0; t < TS; t++) {
        // gen(t-1) overlapped with step-t gate GEMVs inside one launch
        k_step<<<GEN_BLOCKS + 4*(G4/8), 256>>>(Wx0, Wh0, Wh1, Wgen, bgen,
                                               out, t, t - 1, GEN_BLOCKS);
        k_act0 <<<(B*H)/256, 256>>>(b0);
        k_g1p0 <<<G4/8, 256>>>(Wx1);
        k_attn <<<B, 256>>>(mb, mlen, b1, attn_out, t);
        k_wc   <<<H/8, 256>>>(Wc);
    }
    // final generator (t = TS-1), gen blocks only
    k_step<<<GEN_BLOCKS, 256>>>(Wx0, Wh0, Wh1, Wgen, bgen,
                                out, 0, TS - 1, GEN_BLOCKS);
    k_lsm<<<dim3(V/256, B, TS), 256>>>(out);
}

// round 8
// speedup vs baseline: 1.1675x; 1.1675x over previous
#include <cuda_runtime.h>
#include <cstdint>
#include <math.h>

#define TS 63
#define B 32
#define S 256
#define H 512
#define V 32000
#define G4 2048
typedef unsigned long long ull;

// ------------------------- device scratch -----------------------------------
__device__ float g_h[2][B*H];
__device__ float g_c[2][B*H];
__device__ float g_emb[TS][B*H];
__device__ float g_dec[B*H];        // input_feed / dec_out (b-major)
__device__ float g_decT[H*B];       // dec_out transposed [k][b]
__device__ float g_ctx[B*H];
__device__ float g_part0[3][G4*B];
__device__ float g_part1[2][G4*B];
__device__ float g_WaT[H*H];
__device__ float g_sumZ[TS*B];

// ------------------------- f32x2 / cp.async helpers --------------------------
__device__ __forceinline__ ull fma2(ull a, ull b, ull c) {
    ull d; asm("fma.rn.f32x2 %0, %1, %2, %3;" : "=l"(d) : "l"(a), "l"(b), "l"(c));
    return d;
}
__device__ __forceinline__ ull dup2(float x) {
    ull d; asm("mov.b64 %0, {%1, %1};" : "=l"(d) : "f"(x));
    return d;
}
__device__ __forceinline__ void unpack2(ull v, float& lo, float& hi) {
    asm("mov.b64 {%0, %1}, %2;" : "=f"(lo), "=f"(hi) : "l"(v));
}
__device__ __forceinline__ void cp16(uint32_t dst, const void* src) {
    asm volatile("cp.async.cg.shared.global [%0], [%1], 16;" :: "r"(dst), "l"(src));
}
__device__ __forceinline__ void cp_commit() {
    asm volatile("cp.async.commit_group;");
}
template <int N>
__device__ __forceinline__ void cp_wait() {
    asm volatile("cp.async.wait_group %0;" :: "n"(N));
}

// ------------------------- shared-memory union --------------------------------
struct GenSmem {
    float Ws[2][4096];      // per buf: 4 k4-pages x 256 swizzled 16B granules (16KB)
    float Xs[2][512];       // per buf: [k (16)][b (32)]
    float red[8*32];        // [warp][b]
};
union StepSmem {
    float   gemv[8][33*32]; // 33792 B
    GenSmem gen;            // 37888 B
};

// ------------------------- warp GEMV helpers (LSTM path) ---------------------
__device__ __forceinline__ void warp_gemv_acc(const float* __restrict__ Wrow,
                                              const float* __restrict__ X,
                                              float acc[B]) {
    const int lane = threadIdx.x & 31;
#pragma unroll
    for (int kk = 0; kk < 4; kk++) {
        const int k = kk*128 + lane*4;
        const float4 w = *reinterpret_cast<const float4*>(Wrow + k);
#pragma unroll
        for (int b = 0; b < B; b++) {
            const float4 x = *reinterpret_cast<const float4*>(X + b*H + k);
            acc[b] += w.x*x.x + w.y*x.y + w.z*x.z + w.w*x.w;
        }
    }
}
__device__ __forceinline__ float warp_reduce_b(float acc[B], float* sm) {
    const int lane = threadIdx.x & 31;
#pragma unroll
    for (int b = 0; b < B; b++) sm[b*33 + lane] = acc[b];
    __syncwarp();
    float s = 0.f;
#pragma unroll
    for (int j = 0; j < 32; j++) s += sm[lane*33 + j];
    return s;
}

__device__ __forceinline__ float sigm(float x) { return 1.f/(1.f+expf(-x)); }

// swizzled granule index for W smem (conflict-free for both ST and compute LD)
__device__ __forceinline__ int swz(int n) {
    return (n & ~7) | ((n & 7) ^ ((n >> 3) & 7));
}

// ------------------------- generator tile (256 threads, 256 n) ---------------
// thread (ng = tid>>2, bg = tid&3) owns 4n x 8b. K chunked by 16, double-buffered.
__device__ void gen_tile(int tileIdx, int tGen,
                         const float* __restrict__ Wgen,
                         const float* __restrict__ bgen,
                         float* __restrict__ out, GenSmem& g) {
    const int tid = threadIdx.x;
    const int bg = tid & 3, ng = tid >> 2;            // 64 ngroups x 4 bgroups
    const int warp = tid >> 5, lane = tid & 31;
    const int nt = tileIdx * 256;

    uint32_t wsB[2], xsB[2];
    wsB[0] = (uint32_t)__cvta_generic_to_shared(&g.Ws[0][0]);
    wsB[1] = (uint32_t)__cvta_generic_to_shared(&g.Ws[1][0]);
    xsB[0] = (uint32_t)__cvta_generic_to_shared(&g.Xs[0][0]);
    xsB[1] = (uint32_t)__cvta_generic_to_shared(&g.Xs[1][0]);

    const int cp_k4 = tid & 3, cp_nq = tid >> 2;      // W copy mapping
    const float* wsrc = Wgen + (size_t)(nt + cp_nq)*H + cp_k4*4;

    auto prefetch = [&](int c, int buf) {
#pragma unroll
        for (int p = 0; p < 4; p++) {
            int n = cp_nq + p*64;
            cp16(wsB[buf] + (uint32_t)(cp_k4*256 + swz(n))*16,
                 wsrc + (size_t)p*64*H + c*16);
        }
        if (tid < 128) {
            int k = tid >> 3, b4 = tid & 7;
            cp16(xsB[buf] + (uint32_t)(k*32 + b4*4)*4,
                 g_decT + (c*16 + k)*32 + b4*4);
        }
        cp_commit();
    };

    // per-thread W read offsets (float index within a k4 page)
    int wf[4];
#pragma unroll
    for (int i = 0; i < 4; i++) wf[i] = swz(ng*4 + i)*4;

    ull acc[4][4] = {};                               // [n_i][b-pair]

    prefetch(0, 0);
    prefetch(1, 1);

    for (int c = 0; c < 32; c++) {
        if (c < 30) cp_wait<1>(); else cp_wait<0>();
        __syncthreads();
        const int buf = c & 1;
        const float* W = &g.Ws[buf][0];
        const float* X = &g.Xs[buf][0];
#pragma unroll
        for (int kk4 = 0; kk4 < 4; kk4++) {
            float4 wv[4];
#pragma unroll
            for (int i = 0; i < 4; i++)
                wv[i] = *reinterpret_cast<const float4*>(W + kk4*1024 + wf[i]);
#pragma unroll
            for (int k = 0; k < 4; k++) {
                const ull* xp = reinterpret_cast<const ull*>(X + (kk4*4 + k)*32 + bg*8);
                ull x0 = xp[0], x1 = xp[1], x2 = xp[2], x3 = xp[3];
#pragma unroll
                for (int i = 0; i < 4; i++) {
                    float w = (k == 0) ? wv[i].x : (k == 1) ? wv[i].y
                             : (k == 2) ? wv[i].z : wv[i].w;
                    ull wd = dup2(w);
                    acc[i][0] = fma2(wd, x0, acc[i][0]);
                    acc[i][1] = fma2(wd, x1, acc[i][1]);
                    acc[i][2] = fma2(wd, x2, acc[i][2]);
                    acc[i][3] = fma2(wd, x3, acc[i][3]);
                }
            }
        }
        __syncthreads();
        if (c + 2 < 32) prefetch(c + 2, buf);
    }

    // ---- epilogue: bias, store logits, fused exp-sum ----
    float sv[4][8];
#pragma unroll
    for (int i = 0; i < 4; i++) {
        float bb = bgen[nt + ng*4 + i];
#pragma unroll
        for (int p = 0; p < 4; p++) {
            unpack2(acc[i][p], sv[i][2*p], sv[i][2*p+1]);
            sv[i][2*p]   += bb;
            sv[i][2*p+1] += bb;
        }
    }
    float es[8];
#pragma unroll
    for (int j = 0; j < 8; j++) {
        int b = bg*8 + j;
        float* orow = out + ((size_t)(tGen*B + b))*V + nt + ng*4;
        *reinterpret_cast<float4*>(orow) =
            make_float4(sv[0][j], sv[1][j], sv[2][j], sv[3][j]);
        es[j] = expf(sv[0][j]) + expf(sv[1][j]) + expf(sv[2][j]) + expf(sv[3][j]);
    }
    // reduce es over the warp's 8 ngroups (lanes with equal bg)
#pragma unroll
    for (int off = 16; off >= 4; off >>= 1)
#pragma unroll
        for (int j = 0; j < 8; j++)
            es[j] += __shfl_xor_sync(0xffffffffu, es[j], off);
    if (lane < 4) {
#pragma unroll
        for (int j = 0; j < 8; j++) g.red[warp*32 + bg*8 + j] = es[j];
    }
    __syncthreads();
    if (tid < 32) {
        float ssum = 0.f;
#pragma unroll
        for (int w = 0; w < 8; w++) ssum += g.red[w*32 + tid];
        atomicAdd(&g_sumZ[tGen*B + tid], ssum);
    }
}

// ------------------------- kernels ------------------------------------------
__global__ void __launch_bounds__(256) k_init(const float* __restrict__ eh,
                                              const float* __restrict__ ec,
                                              const float* __restrict__ Wa) {
    int idx = blockIdx.x*256 + threadIdx.x;          // grid covers H*H
    if (idx < 2*B*H) { (&g_h[0][0])[idx] = eh[idx]; (&g_c[0][0])[idx] = ec[idx]; }
    if (idx < B*H)   { g_dec[idx] = 0.f; g_decT[idx] = 0.f; }
    if (idx < TS*B)  g_sumZ[idx] = 0.f;
    if (idx < H*H)   { int h = idx / H; int k = idx - h*H; g_WaT[k*H + h] = Wa[idx]; }
}

__global__ void __launch_bounds__(256) k_embed(const int* __restrict__ tgt,
                                               const float* __restrict__ et) {
    int idx = blockIdx.x*256 + threadIdx.x;          // < TS*B*H
    int e = idx & (H - 1);
    int r = idx >> 9;                                 // t*B + b
    int tok = tgt[r];
    (&g_emb[0][0])[idx] = et[(size_t)tok*H + e];
}

// Merged: generator for step tGen (blocks 0..genBlocks-1) + 4 gate GEMVs for
// step t (remaining blocks). The two halves are data-independent.
__global__ void __launch_bounds__(256) k_step(const float* __restrict__ Wx0,
                                              const float* __restrict__ Wh0,
                                              const float* __restrict__ Wh1,
                                              const float* __restrict__ Wgen,
                                              const float* __restrict__ bgen,
                                              float* __restrict__ out,
                                              int t, int tGen, int genBlocks) {
    __shared__ StepSmem u;
    if ((int)blockIdx.x < genBlocks) {
        if (tGen < 0) return;
        gen_tile(blockIdx.x, tGen, Wgen, bgen, out, u.gen);
        return;
    }
    const int blk = blockIdx.x - genBlocks;           // 0..1023
    const int p = blk >> 8, nb = blk & 255;
    const int warp = threadIdx.x >> 5, lane = threadIdx.x & 31;
    const int n = nb*8 + warp;                        // 0..2047
    const float* Wrow; const float* X; float* dst;
    if (p == 0)      { Wrow = Wx0 + (size_t)n*1024;        X = g_emb[t]; dst = &g_part0[0][0]; }
    else if (p == 1) { Wrow = Wx0 + (size_t)n*1024 + 512;  X = g_dec;    dst = &g_part0[1][0]; }
    else if (p == 2) { Wrow = Wh0 + (size_t)n*512;         X = g_h[0];   dst = &g_part0[2][0]; }
    else             { Wrow = Wh1 + (size_t)n*512;         X = g_h[1];   dst = &g_part1[1][0]; }
    float acc[B] = {};
    warp_gemv_acc(Wrow, X, acc);
    float s = warp_reduce_b(acc, u.gemv[warp]);
    dst[n*B + lane] = s;
}

// Wx1 x h0 (needs act0 output) -> part1[0]
__global__ void __launch_bounds__(256) k_g1p0(const float* __restrict__ Wx1) {
    __shared__ float sm[8][33*32];
    const int warp = threadIdx.x >> 5, lane = threadIdx.x & 31;
    const int n = blockIdx.x*8 + warp;
    float acc[B] = {};
    warp_gemv_acc(Wx1 + (size_t)n*512, g_h[0], acc);
    float s = warp_reduce_b(acc, sm[warp]);
    g_part1[0][n*B + lane] = s;
}

// Layer-0 activation (3 partials)
__global__ void __launch_bounds__(256) k_act0(const float* __restrict__ bias) {
    int idx = blockIdx.x*256 + threadIdx.x;           // < B*H
    int b = idx & 31, j = idx >> 5;
    float gi = bias[j], gf = bias[512+j], gg = bias[1024+j], go = bias[1536+j];
#pragma unroll
    for (int p = 0; p < 3; p++) {
        const float* pp = &g_part0[p][0];
        gi += pp[(j       )*B + b];
        gf += pp[(512 + j )*B + b];
        gg += pp[(1024 + j)*B + b];
        go += pp[(1536 + j)*B + b];
    }
    float c  = g_c[0][b*H + j];
    float cn = sigm(gf)*c + sigm(gi)*tanhf(gg);
    g_c[0][b*H + j] = cn;
    g_h[0][b*H + j] = sigm(go)*tanhf(cn);
}

// Fused: layer-1 activation + q projection + attention + context. One block per batch.
__global__ void __launch_bounds__(256) k_attn(const float* __restrict__ mb,
                                              const int* __restrict__ mlen,
                                              const float* __restrict__ b1v,
                                              float* __restrict__ attn_out, int t) {
    __shared__ float sh1[H];
    __shared__ float sq[H];
    __shared__ float al[S];
    __shared__ float red[256];
    const int b = blockIdx.x;
    const int tid = threadIdx.x, warp = tid >> 5, lane = tid & 31;
    const int len = mlen[b];

    // ---- act1 for this batch ----
    for (int j = tid; j < H; j += 256) {
        float gi = b1v[j], gf = b1v[512+j], gg = b1v[1024+j], go = b1v[1536+j];
#pragma unroll
        for (int p = 0; p < 2; p++) {
            const float* pp = &g_part1[p][0];
            gi += pp[(j       )*B + b];
            gf += pp[(512 + j )*B + b];
            gg += pp[(1024 + j)*B + b];
            go += pp[(1536 + j)*B + b];
        }
        float c  = g_c[1][b*H + j];
        float cn = sigm(gf)*c + sigm(gi)*tanhf(gg);
        g_c[1][b*H + j] = cn;
        float hn = sigm(go)*tanhf(cn);
        g_h[1][b*H + j] = hn;
        sh1[j] = hn;
    }
    __syncthreads();

    // ---- q[n] = sum_k h1[k] * Wa[k][n] — warp per row (coalesced) ----
    for (int n0 = warp; n0 < H; n0 += 8) {
        const float* wr = g_WaT + (size_t)n0*H;
        float a = 0.f;
#pragma unroll
        for (int kk = 0; kk < 4; kk++) {
            int k = kk*128 + lane*4;
            float4 w  = *reinterpret_cast<const float4*>(wr + k);
            float4 hx = *reinterpret_cast<const float4*>(sh1 + k);
            a += w.x*hx.x + w.y*hx.y + w.z*hx.z + w.w*hx.w;
        }
#pragma unroll
        for (int off = 16; off; off >>= 1) a += __shfl_xor_sync(0xffffffffu, a, off);
        if (lane == 0) sq[n0] = a;
    }
    __syncthreads();

    // ---- alignment scores ----
    for (int s0 = warp; s0 < S; s0 += 8) {
        const float* m = mb + ((size_t)s0*B + b)*H;
        float a = 0.f;
#pragma unroll
        for (int kk = 0; kk < 4; kk++) {
            int k = kk*128 + lane*4;
            float4 mv = *reinterpret_cast<const float4*>(m + k);
            float4 qv = *reinterpret_cast<const float4*>(sq + k);
            a += mv.x*qv.x + mv.y*qv.y + mv.z*qv.z + mv.w*qv.w;
        }
#pragma unroll
        for (int off = 16; off; off >>= 1) a += __shfl_xor_sync(0xffffffffu, a, off);
        if (lane == 0) al[s0] = (s0 < len) ? a : -1.0e9f;
    }
    __syncthreads();

    // ---- softmax over S=256 ----
    float v = al[tid];
    red[tid] = v; __syncthreads();
    for (int o = 128; o; o >>= 1) { if (tid < o) red[tid] = fmaxf(red[tid], red[tid+o]); __syncthreads(); }
    float vmax = red[0];
    __syncthreads();
    float e = expf(v - vmax);
    red[tid] = e; __syncthreads();
    for (int o = 128; o; o >>= 1) { if (tid < o) red[tid] += red[tid+o]; __syncthreads(); }
    float p = e / red[0];
    al[tid] = p;
    attn_out[((size_t)t*B + b)*S + tid] = p;
    __syncthreads();

    // ---- context ----
    for (int k = tid; k < H; k += 256) {
        float acc = 0.f;
#pragma unroll 4
        for (int s = 0; s < S; s++) acc += al[s] * mb[((size_t)s*B + b)*H + k];
        g_ctx[b*H + k] = acc;
    }
}

__global__ void __launch_bounds__(256) k_wc(const float* __restrict__ Wc) {
    __shared__ float sm[8][33*32];
    const int warp = threadIdx.x >> 5, lane = threadIdx.x & 31;
    const int n = blockIdx.x*8 + warp;                // 0..511
    float acc[B] = {};
    warp_gemv_acc(Wc + (size_t)n*1024,       g_ctx,  acc);
    warp_gemv_acc(Wc + (size_t)n*1024 + 512, g_h[1], acc);
    float s = warp_reduce_b(acc, sm[warp]);
    float d = tanhf(s);
    g_dec [lane*H + n] = d;
    g_decT[n*B + lane] = d;                           // transposed copy for gen
}

// one pass at the end over all timesteps
__global__ void __launch_bounds__(256) k_lsm(float* __restrict__ out) {
    __shared__ float lz;
    const int t = blockIdx.z, b = blockIdx.y;
    if (threadIdx.x == 0) lz = logf(g_sumZ[t*B + b]);
    __syncthreads();
    int v = blockIdx.x*256 + threadIdx.x;
    out[((size_t)(t*B + b))*V + v] -= lz;
}

// ------------------------- launch -------------------------------------------
extern "C" void kernel_launch(void* const* d_in, const int* in_sizes, int n_in,
                              void* d_out, int out_size) {
    const int*   tgt   = (const int*)  d_in[0];
    const float* mb    = (const float*)d_in[1];
    const int*   mlen  = (const int*)  d_in[2];
    const float* enc_h = (const float*)d_in[3];
    const float* enc_c = (const float*)d_in[4];
    const float* emb   = (const float*)d_in[5];
    const float* Wx0   = (const float*)d_in[6];
    const float* Wh0   = (const float*)d_in[7];
    const float* b0    = (const float*)d_in[8];
    const float* Wx1   = (const float*)d_in[9];
    const float* Wh1   = (const float*)d_in[10];
    const float* b1    = (const float*)d_in[11];
    const float* Wa    = (const float*)d_in[12];
    const float* Wc    = (const float*)d_in[13];
    const float* Wgen  = (const float*)d_in[14];
    const float* bgen  = (const float*)d_in[15];

    float* out      = (float*)d_out;
    float* attn_out = out + (size_t)TS*B*V;

    const int GEN_BLOCKS = V/256;                     // 125

    k_init <<<(H*H + 255)/256, 256>>>(enc_h, enc_c, Wa);
    k_embed<<<(TS*B*H)/256, 256>>>(tgt, emb);

    for (int t = 0; t < TS; t++) {
        // gen(t-1) overlapped with step-t gate GEMVs inside one launch
        k_step<<<GEN_BLOCKS + 4*(G4/8), 256>>>(Wx0, Wh0, Wh1, Wgen, bgen,
                                               out, t, t - 1, GEN_BLOCKS);
        k_act0 <<<(B*H)/256, 256>>>(b0);
        k_g1p0 <<<G4/8, 256>>>(Wx1);
        k_attn <<<B, 256>>>(mb, mlen, b1, attn_out, t);
        k_wc   <<<H/8, 256>>>(Wc);
    }
    // final generator (t = TS-1), gen blocks only
    k_step<<<GEN_BLOCKS, 256>>>(Wx0, Wh0, Wh1, Wgen, bgen,
                                out, 0, TS - 1, GEN_BLOCKS);
    k_lsm<<<dim3(V/256, B, TS), 256>>>(out);
}

// round 10
// speedup vs baseline: 1.3979x; 1.1973x over previous
#include <cuda_runtime.h>
#include <cuda_bf16.h>
#include <cstdint>
#include <math.h>

#define TS 63
#define B 32
#define S 256
#define H 512
#define V 32000
#define G4 2048
#define NG (V/16)              /* 2000 A-row groups */
#define KC (H/16)              /* 32 k-chunks */

// ------------------------- device scratch -----------------------------------
__device__ float g_h[2][B*H];
__device__ float g_c[2][B*H];
__device__ float g_emb[TS][B*H];
__device__ float g_dec[B*H];
__device__ float g_ctx[B*H];
__device__ float g_part0[3][G4*B];
__device__ float g_part1[2][G4*B];
__device__ float g_WaT[H*H];
__device__ float g_sumZ[TS*B];
// A fragments: [g (2000)][c (32)][lane (32)][reg (8: a0..a3 hi, a0..a3 lo)]
__device__ __align__(16) uint32_t g_Wq[(size_t)NG*KC*32*8];
// B fragments: [bg (4)][c (32)][lane (32)] -> uint4 {b0hi,b1hi,b0lo,b1lo}
__device__ __align__(16) uint32_t g_xq[4*KC*32*4];

// ------------------------- helpers -------------------------------------------
__device__ __forceinline__ void mma16816(float c[4], const uint32_t a[4],
                                         uint32_t b0, uint32_t b1) {
    asm volatile("mma.sync.aligned.m16n8k16.row.col.f32.bf16.bf16.f32 "
        "{%0,%1,%2,%3}, {%4,%5,%6,%7}, {%8,%9}, {%0,%1,%2,%3};"
        : "+f"(c[0]), "+f"(c[1]), "+f"(c[2]), "+f"(c[3])
        : "r"(a[0]), "r"(a[1]), "r"(a[2]), "r"(a[3]), "r"(b0), "r"(b1));
}
__device__ __forceinline__ uint32_t pack_bf16(float x, float y) {
    __nv_bfloat162 v = __floats2bfloat162_rn(x, y);   // low = x, high = y
    return *reinterpret_cast<uint32_t*>(&v);
}
__device__ __forceinline__ float bf16_hi_f(float x) {
    __nv_bfloat16 h = __float2bfloat16_rn(x);
    return __bfloat162float(h);
}

// ------------------------- warp GEMV helpers (LSTM path) ---------------------
__device__ __forceinline__ void warp_gemv_acc(const float* __restrict__ Wrow,
                                              const float* __restrict__ X,
                                              float acc[B]) {
    const int lane = threadIdx.x & 31;
#pragma unroll
    for (int kk = 0; kk < 4; kk++) {
        const int k = kk*128 + lane*4;
        const float4 w = *reinterpret_cast<const float4*>(Wrow + k);
#pragma unroll
        for (int b = 0; b < B; b++) {
            const float4 x = *reinterpret_cast<const float4*>(X + b*H + k);
            acc[b] += w.x*x.x + w.y*x.y + w.z*x.z + w.w*x.w;
        }
    }
}
__device__ __forceinline__ float warp_reduce_b(float acc[B], float* sm) {
    const int lane = threadIdx.x & 31;
#pragma unroll
    for (int b = 0; b < B; b++) sm[b*33 + lane] = acc[b];
    __syncwarp();
    float s = 0.f;
#pragma unroll
    for (int j = 0; j < 32; j++) s += sm[lane*33 + j];
    return s;
}
__device__ __forceinline__ float sigm(float x) { return 1.f/(1.f+expf(-x)); }

// ------------------------- kernels ------------------------------------------
__global__ void __launch_bounds__(256) k_init(const float* __restrict__ eh,
                                              const float* __restrict__ ec,
                                              const float* __restrict__ Wa) {
    int idx = blockIdx.x*256 + threadIdx.x;          // grid covers H*H
    if (idx < 2*B*H) { (&g_h[0][0])[idx] = eh[idx]; (&g_c[0][0])[idx] = ec[idx]; }
    if (idx < B*H)   g_dec[idx] = 0.f;
    if (idx < TS*B)  g_sumZ[idx] = 0.f;
    if (idx < H*H)   { int h = idx / H; int k = idx - h*H; g_WaT[k*H + h] = Wa[idx]; }
}

__global__ void __launch_bounds__(256) k_embed(const int* __restrict__ tgt,
                                               const float* __restrict__ et) {
    int idx = blockIdx.x*256 + threadIdx.x;          // < TS*B*H
    int e = idx & (H - 1);
    int r = idx >> 9;
    int tok = tgt[r];
    (&g_emb[0][0])[idx] = et[(size_t)tok*H + e];
}

// Pack Wgen into per-lane mma A-fragment order (hi/lo bf16 split).
// idx = (((g*KC + c)*32) + lane)*8 + reg
__global__ void __launch_bounds__(256) k_pack(const float* __restrict__ Wgen) {
    int idx = blockIdx.x*256 + threadIdx.x;          // < NG*KC*32*8
    int reg  = idx & 7;
    int lane = (idx >> 3) & 31;
    int c    = (idx >> 8) & 31;
    int g    = idx >> 13;
    int split = reg >> 2, r4 = reg & 3;
    int gid = lane >> 2, tig = lane & 3;
    int n = g*16 + gid + ((r4 & 1) ? 8 : 0);
    int k = c*16 + tig*2 + ((r4 & 2) ? 8 : 0);
    float w0 = Wgen[(size_t)n*H + k];
    float w1 = Wgen[(size_t)n*H + k + 1];
    float h0 = bf16_hi_f(w0), h1 = bf16_hi_f(w1);
    uint32_t v;
    if (split == 0) v = pack_bf16(h0, h1);
    else            v = pack_bf16(w0 - h0, w1 - h1);
    g_Wq[idx] = v;
}

// Pack dec into mma B-fragments (hi/lo). 4096 threads.
__global__ void __launch_bounds__(256) k_xpack() {
    int idx = blockIdx.x*256 + threadIdx.x;          // < 4*KC*32
    int lane = idx & 31;
    int c    = (idx >> 5) & 31;
    int bg   = idx >> 10;
    int gid = lane >> 2, tig = lane & 3;
    int b = bg*8 + gid;
    const float* xp = g_dec + (size_t)b*H + c*16 + tig*2;
    float x0 = xp[0], x1 = xp[1], x2 = xp[8], x3 = xp[9];
    float h0 = bf16_hi_f(x0), h1 = bf16_hi_f(x1), h2 = bf16_hi_f(x2), h3 = bf16_hi_f(x3);
    uint4 v;
    v.x = pack_bf16(h0, h1);
    v.y = pack_bf16(h2, h3);
    v.z = pack_bf16(x0 - h0, x1 - h1);
    v.w = pack_bf16(x2 - h2, x3 - h3);
    *reinterpret_cast<uint4*>(&g_xq[idx*4]) = v;
}

// 4 independent gate GEMVs
__global__ void __launch_bounds__(256) k_gemms(const float* __restrict__ Wx0,
                                               const float* __restrict__ Wh0,
                                               const float* __restrict__ Wh1, int t) {
    __shared__ float sm[8][33*32];
    const int warp = threadIdx.x >> 5, lane = threadIdx.x & 31;
    const int n = blockIdx.x*8 + warp;
    const int p = blockIdx.y;
    const float* Wrow; const float* X; float* dst;
    if (p == 0)      { Wrow = Wx0 + (size_t)n*1024;        X = g_emb[t]; dst = &g_part0[0][0]; }
    else if (p == 1) { Wrow = Wx0 + (size_t)n*1024 + 512;  X = g_dec;    dst = &g_part0[1][0]; }
    else if (p == 2) { Wrow = Wh0 + (size_t)n*512;         X = g_h[0];   dst = &g_part0[2][0]; }
    else             { Wrow = Wh1 + (size_t)n*512;         X = g_h[1];   dst = &g_part1[1][0]; }
    float acc[B] = {};
    warp_gemv_acc(Wrow, X, acc);
    float s = warp_reduce_b(acc, sm[warp]);
    dst[n*B + lane] = s;
}

__global__ void __launch_bounds__(256) k_g1p0(const float* __restrict__ Wx1) {
    __shared__ float sm[8][33*32];
    const int warp = threadIdx.x >> 5, lane = threadIdx.x & 31;
    const int n = blockIdx.x*8 + warp;
    float acc[B] = {};
    warp_gemv_acc(Wx1 + (size_t)n*512, g_h[0], acc);
    float s = warp_reduce_b(acc, sm[warp]);
    g_part1[0][n*B + lane] = s;
}

__global__ void __launch_bounds__(256) k_act0(const float* __restrict__ bias) {
    int idx = blockIdx.x*256 + threadIdx.x;
    int b = idx & 31, j = idx >> 5;
    float gi = bias[j], gf = bias[512+j], gg = bias[1024+j], go = bias[1536+j];
#pragma unroll
    for (int p = 0; p < 3; p++) {
        const float* pp = &g_part0[p][0];
        gi += pp[(j       )*B + b];
        gf += pp[(512 + j )*B + b];
        gg += pp[(1024 + j)*B + b];
        go += pp[(1536 + j)*B + b];
    }
    float c  = g_c[0][b*H + j];
    float cn = sigm(gf)*c + sigm(gi)*tanhf(gg);
    g_c[0][b*H + j] = cn;
    g_h[0][b*H + j] = sigm(go)*tanhf(cn);
}

// Fused: layer-1 activation + q projection + attention + context.
__global__ void __launch_bounds__(256) k_attn(const float* __restrict__ mb,
                                              const int* __restrict__ mlen,
                                              const float* __restrict__ b1v,
                                              float* __restrict__ attn_out, int t) {
    __shared__ float sh1[H];
    __shared__ float sq[H];
    __shared__ float al[S];
    __shared__ float red[256];
    const int b = blockIdx.x;
    const int tid = threadIdx.x, warp = tid >> 5, lane = tid & 31;
    const int len = mlen[b];

    for (int j = tid; j < H; j += 256) {
        float gi = b1v[j], gf = b1v[512+j], gg = b1v[1024+j], go = b1v[1536+j];
#pragma unroll
        for (int p = 0; p < 2; p++) {
            const float* pp = &g_part1[p][0];
            gi += pp[(j       )*B + b];
            gf += pp[(512 + j )*B + b];
            gg += pp[(1024 + j)*B + b];
            go += pp[(1536 + j)*B + b];
        }
        float c  = g_c[1][b*H + j];
        float cn = sigm(gf)*c + sigm(gi)*tanhf(gg);
        g_c[1][b*H + j] = cn;
        float hn = sigm(go)*tanhf(cn);
        g_h[1][b*H + j] = hn;
        sh1[j] = hn;
    }
    __syncthreads();

    for (int n0 = warp; n0 < H; n0 += 8) {
        const float* wr = g_WaT + (size_t)n0*H;
        float a = 0.f;
#pragma unroll
        for (int kk = 0; kk < 4; kk++) {
            int k = kk*128 + lane*4;
            float4 w  = *reinterpret_cast<const float4*>(wr + k);
            float4 hx = *reinterpret_cast<const float4*>(sh1 + k);
            a += w.x*hx.x + w.y*hx.y + w.z*hx.z + w.w*hx.w;
        }
#pragma unroll
        for (int off = 16; off; off >>= 1) a += __shfl_xor_sync(0xffffffffu, a, off);
        if (lane == 0) sq[n0] = a;
    }
    __syncthreads();

    for (int s0 = warp; s0 < S; s0 += 8) {
        const float* m = mb + ((size_t)s0*B + b)*H;
        float a = 0.f;
#pragma unroll
        for (int kk = 0; kk < 4; kk++) {
            int k = kk*128 + lane*4;
            float4 mv = *reinterpret_cast<const float4*>(m + k);
            float4 qv = *reinterpret_cast<const float4*>(sq + k);
            a += mv.x*qv.x + mv.y*qv.y + mv.z*qv.z + mv.w*qv.w;
        }
#pragma unroll
        for (int off = 16; off; off >>= 1) a += __shfl_xor_sync(0xffffffffu, a, off);
        if (lane == 0) al[s0] = (s0 < len) ? a : -1.0e9f;
    }
    __syncthreads();

    float v = al[tid];
    red[tid] = v; __syncthreads();
    for (int o = 128; o; o >>= 1) { if (tid < o) red[tid] = fmaxf(red[tid], red[tid+o]); __syncthreads(); }
    float vmax = red[0];
    __syncthreads();
    float e = expf(v - vmax);
    red[tid] = e; __syncthreads();
    for (int o = 128; o; o >>= 1) { if (tid < o) red[tid] += red[tid+o]; __syncthreads(); }
    float p = e / red[0];
    al[tid] = p;
    attn_out[((size_t)t*B + b)*S + tid] = p;
    __syncthreads();

    for (int k = tid; k < H; k += 256) {
        float acc = 0.f;
#pragma unroll 4
        for (int s = 0; s < S; s++) acc += al[s] * mb[((size_t)s*B + b)*H + k];
        g_ctx[b*H + k] = acc;
    }
}

__global__ void __launch_bounds__(256) k_wc(const float* __restrict__ Wc) {
    __shared__ float sm[8][33*32];
    const int warp = threadIdx.x >> 5, lane = threadIdx.x & 31;
    const int n = blockIdx.x*8 + warp;                // 0..511
    float acc[B] = {};
    warp_gemv_acc(Wc + (size_t)n*1024,       g_ctx,  acc);
    warp_gemv_acc(Wc + (size_t)n*1024 + 512, g_h[1], acc);
    float s = warp_reduce_b(acc, sm[warp]);
    g_dec[lane*H + n] = tanhf(s);
}

// ------------------------- generator via mma.sync bf16 -----------------------
// 250 blocks x 256 threads. Warp w computes rows [blk*128 + w*16, +16) x all 32 b.
__global__ void __launch_bounds__(256) k_tgen(const float* __restrict__ bgen,
                                              float* __restrict__ out, int t) {
    __shared__ float Dsm[128*33];
    const int tid = threadIdx.x;
    const int wid = tid >> 5, lane = tid & 31;
    const int gid = lane >> 2, tig = lane & 3;
    const int nt = blockIdx.x * 128;

    const int ngrp = blockIdx.x*8 + wid;              // 0..1999
    const uint32_t* wq = g_Wq + (size_t)ngrp*KC*32*8;

    float acc[4][4] = {};                             // [bg][reg]

    for (int c = 0; c < KC; c++) {
        const uint32_t* ap = wq + (c*32 + lane)*8;
        uint4 ahiv = *reinterpret_cast<const uint4*>(ap);
        uint4 alov = *reinterpret_cast<const uint4*>(ap + 4);
        uint32_t ahi[4] = {ahiv.x, ahiv.y, ahiv.z, ahiv.w};
        uint32_t alo[4] = {alov.x, alov.y, alov.z, alov.w};
#pragma unroll
        for (int bg = 0; bg < 4; bg++) {
            uint4 xb = *reinterpret_cast<const uint4*>(&g_xq[((bg*KC + c)*32 + lane)*4]);
            mma16816(acc[bg], ahi, xb.x, xb.y);       // whi * xhi
            mma16816(acc[bg], ahi, xb.z, xb.w);       // whi * xlo
            mma16816(acc[bg], alo, xb.x, xb.y);       // wlo * xhi
        }
    }

    // scatter fragments to smem [n_local][b]
#pragma unroll
    for (int bg = 0; bg < 4; bg++) {
#pragma unroll
        for (int r = 0; r < 4; r++) {
            int nl = wid*16 + gid + ((r >= 2) ? 8 : 0);
            int b  = bg*8 + tig*2 + (r & 1);
            Dsm[nl*33 + b] = acc[bg][r];
        }
    }
    __syncthreads();

    // epilogue: bias, store logits (coalesced in n), fused exp-sum
    const int n = tid & 127, bh = tid >> 7;
    const float bias = bgen[nt + n];
    float* obase = out + (size_t)t*B*V + nt + n;
#pragma unroll
    for (int j = 0; j < 16; j++) {
        int b = bh*16 + j;
        float v = Dsm[n*33 + b] + bias;
        obase[(size_t)b*V] = v;
        Dsm[n*33 + b] = expf(v);
    }
    __syncthreads();
    if (tid < 32) {
        float s = 0.f;
#pragma unroll 8
        for (int nn = 0; nn < 128; nn++) s += Dsm[nn*33 + tid];
        atomicAdd(&g_sumZ[t*B + tid], s);
    }
}

// one pass at the end over all timesteps
__global__ void __launch_bounds__(256) k_lsm(float* __restrict__ out) {
    __shared__ float lz;
    const int t = blockIdx.z, b = blockIdx.y;
    if (threadIdx.x == 0) lz = logf(g_sumZ[t*B + b]);
    __syncthreads();
    int v = blockIdx.x*256 + threadIdx.x;
    out[((size_t)(t*B + b))*V + v] -= lz;
}

// ------------------------- launch -------------------------------------------
extern "C" void kernel_launch(void* const* d_in, const int* in_sizes, int n_in,
                              void* d_out, int out_size) {
    const int*   tgt   = (const int*)  d_in[0];
    const float* mb    = (const float*)d_in[1];
    const int*   mlen  = (const int*)  d_in[2];
    const float* enc_h = (const float*)d_in[3];
    const float* enc_c = (const float*)d_in[4];
    const float* emb   = (const float*)d_in[5];
    const float* Wx0   = (const float*)d_in[6];
    const float* Wh0   = (const float*)d_in[7];
    const float* b0    = (const float*)d_in[8];
    const float* Wx1   = (const float*)d_in[9];
    const float* Wh1   = (const float*)d_in[10];
    const float* b1    = (const float*)d_in[11];
    const float* Wa    = (const float*)d_in[12];
    const float* Wc    = (const float*)d_in[13];
    const float* Wgen  = (const float*)d_in[14];
    const float* bgen  = (const float*)d_in[15];

    float* out      = (float*)d_out;
    float* attn_out = out + (size_t)TS*B*V;

    k_init <<<(H*H + 255)/256, 256>>>(enc_h, enc_c, Wa);
    k_embed<<<(TS*B*H)/256, 256>>>(tgt, emb);
    k_pack <<<(NG*KC*32*8)/256, 256>>>(Wgen);

    for (int t = 0; t < TS; t++) {
        k_gemms<<<dim3(G4/8, 4), 256>>>(Wx0, Wh0, Wh1, t);
        k_act0 <<<(B*H)/256, 256>>>(b0);
        k_g1p0 <<<G4/8, 256>>>(Wx1);
        k_attn <<<B, 256>>>(mb, mlen, b1, attn_out, t);
        k_wc   <<<H/8, 256>>>(Wc);
        k_xpack<<<(4*KC*32)/256, 256>>>();
        k_tgen <<<V/128, 256>>>(bgen, out, t);
    }
    k_lsm<<<dim3(V/256, B, TS), 256>>>(out);
}

// round 12
// speedup vs baseline: 1.4764x; 1.0562x over previous
#include <cuda_runtime.h>
#include <cuda_bf16.h>
#include <cstdint>
#include <math.h>

#define TS 63
#define B 32
#define S 256
#define H 512
#define V 32000
#define G4 2048
#define NG (V/16)              /* 2000 A-row groups */
#define KC (H/16)              /* 32 k-chunks */
#define XFRAG (4*KC*32*4)      /* 16384 uint32 in the X fragment image */
#define GENB 250               /* V/128 generator blocks */

// ------------------------- device scratch -----------------------------------
__device__ float g_h[2][B*H];
__device__ float g_c[2][B*H];
__device__ float g_emb[TS][B*H];
__device__ float g_dec[B*H];
__device__ float g_ctx[B*H];
__device__ float g_part0[3][G4*B];
__device__ float g_part1[2][G4*B];
__device__ float g_WaT[H*H];
__device__ float g_sumZ[TS*B];
// A fragments: [g (2000)][c (32)][lane (32)][reg (8: a0..a3 hi, a0..a3 lo)]
__device__ __align__(16) uint32_t g_Wq[(size_t)NG*KC*32*8];
// B fragments: [bg (4)][c (32)][lane (32)] -> uint4 {b0hi,b1hi,b0lo,b1lo}
__device__ __align__(16) uint32_t g_xq[XFRAG];

// ------------------------- helpers -------------------------------------------
__device__ __forceinline__ void mma16816(float c[4], const uint32_t a[4],
                                         uint32_t b0, uint32_t b1) {
    asm volatile("mma.sync.aligned.m16n8k16.row.col.f32.bf16.bf16.f32 "
        "{%0,%1,%2,%3}, {%4,%5,%6,%7}, {%8,%9}, {%0,%1,%2,%3};"
        : "+f"(c[0]), "+f"(c[1]), "+f"(c[2]), "+f"(c[3])
        : "r"(a[0]), "r"(a[1]), "r"(a[2]), "r"(a[3]), "r"(b0), "r"(b1));
}
__device__ __forceinline__ uint32_t pack_bf16(float x, float y) {
    __nv_bfloat162 v = __floats2bfloat162_rn(x, y);   // low = x, high = y
    return *reinterpret_cast<uint32_t*>(&v);
}
__device__ __forceinline__ float bf16_hi_f(float x) {
    __nv_bfloat16 h = __float2bfloat16_rn(x);
    return __bfloat162float(h);
}
// scatter one activation value into the B-fragment image (hi + lo halfwords)
__device__ __forceinline__ void scatter_frag(uint32_t* base, int b, int k, float v) {
    int bg = b >> 3, gid = b & 7;
    int c = k >> 4, kk = k & 15;
    int hi8 = kk >> 3, tig = (kk >> 1) & 3, half = kk & 1;
    int lane = gid*4 + tig;
    int idx2 = (bg*KC + c)*32 + lane;
    __nv_bfloat16 hb = __float2bfloat16_rn(v);
    float hv = __bfloat162float(hb);
    __nv_bfloat16 lb = __float2bfloat16_rn(v - hv);
    unsigned short* p16 = reinterpret_cast<unsigned short*>(base);
    p16[(idx2*4 + hi8)*2 + half]       = *reinterpret_cast<unsigned short*>(&hb);
    p16[(idx2*4 + 2 + hi8)*2 + half]   = *reinterpret_cast<unsigned short*>(&lb);
}

// ------------------------- warp GEMV helpers (fp32 LSTM path) ----------------
__device__ __forceinline__ void warp_gemv_acc(const float* __restrict__ Wrow,
                                              const float* __restrict__ X,
                                              float acc[B]) {
    const int lane = threadIdx.x & 31;
#pragma unroll
    for (int kk = 0; kk < 4; kk++) {
        const int k = kk*128 + lane*4;
        const float4 w = *reinterpret_cast<const float4*>(Wrow + k);
#pragma unroll
        for (int b = 0; b < B; b++) {
            const float4 x = *reinterpret_cast<const float4*>(X + b*H + k);
            acc[b] += w.x*x.x + w.y*x.y + w.z*x.z + w.w*x.w;
        }
    }
}
__device__ __forceinline__ float warp_reduce_b(float acc[B], float* sm) {
    const int lane = threadIdx.x & 31;
#pragma unroll
    for (int b = 0; b < B; b++) sm[b*33 + lane] = acc[b];
    __syncwarp();
    float s = 0.f;
#pragma unroll
    for (int j = 0; j < 32; j++) s += sm[lane*33 + j];
    return s;
}
__device__ __forceinline__ float sigm(float x) { return 1.f/(1.f+expf(-x)); }

// ------------------------- shared union for the merged kernel ----------------
union MixSmem {
    float gemv[8][33*32];   // 33792 B
    float Dsm[128*33];      // 16896 B
};

// ------------------------- generator tile (bf16x3 mma) ------------------------
__device__ void gen_tile(int tile, int tGen, const float* __restrict__ bgen,
                         float* __restrict__ out, float* Dsm) {
    const int tid = threadIdx.x;
    const int wid = tid >> 5, lane = tid & 31;
    const int gid = lane >> 2, tig = lane & 3;
    const int nt = tile * 128;

    const int ngrp = tile*8 + wid;                    // 0..1999
    const uint32_t* wq = g_Wq + (size_t)ngrp*KC*32*8;

    float acc[4][4] = {};
    for (int c = 0; c < KC; c++) {
        const uint32_t* ap = wq + (c*32 + lane)*8;
        uint4 ahiv = *reinterpret_cast<const uint4*>(ap);
        uint4 alov = *reinterpret_cast<const uint4*>(ap + 4);
        uint32_t ahi[4] = {ahiv.x, ahiv.y, ahiv.z, ahiv.w};
        uint32_t alo[4] = {alov.x, alov.y, alov.z, alov.w};
#pragma unroll
        for (int bg = 0; bg < 4; bg++) {
            uint4 xb = *reinterpret_cast<const uint4*>(&g_xq[((bg*KC + c)*32 + lane)*4]);
            mma16816(acc[bg], ahi, xb.x, xb.y);
            mma16816(acc[bg], ahi, xb.z, xb.w);
            mma16816(acc[bg], alo, xb.x, xb.y);
        }
    }

#pragma unroll
    for (int bg = 0; bg < 4; bg++) {
#pragma unroll
        for (int r = 0; r < 4; r++) {
            int nl = wid*16 + gid + ((r >= 2) ? 8 : 0);
            int b  = bg*8 + tig*2 + (r & 1);
            Dsm[nl*33 + b] = acc[bg][r];
        }
    }
    __syncthreads();

    const int n = tid & 127, bh = tid >> 7;
    const float bias = bgen[nt + n];
    float* obase = out + (size_t)tGen*B*V + nt + n;
#pragma unroll
    for (int j = 0; j < 16; j++) {
        int b = bh*16 + j;
        float v = Dsm[n*33 + b] + bias;
        obase[(size_t)b*V] = v;
        Dsm[n*33 + b] = expf(v);
    }
    __syncthreads();
    if (tid < 32) {
        float s = 0.f;
#pragma unroll 8
        for (int nn = 0; nn < 128; nn++) s += Dsm[nn*33 + tid];
        atomicAdd(&g_sumZ[tGen*B + tid], s);
    }
}

// ------------------------- kernels ------------------------------------------
__global__ void __launch_bounds__(256) k_init(const float* __restrict__ eh,
                                              const float* __restrict__ ec,
                                              const float* __restrict__ Wa) {
    int idx = blockIdx.x*256 + threadIdx.x;          // grid covers H*H
    if (idx < 2*B*H) { (&g_h[0][0])[idx] = eh[idx]; (&g_c[0][0])[idx] = ec[idx]; }
    if (idx < B*H)   g_dec[idx] = 0.f;
    if (idx < TS*B)  g_sumZ[idx] = 0.f;
    if (idx < H*H)   { int h = idx / H; int k = idx - h*H; g_WaT[k*H + h] = Wa[idx]; }
}

__global__ void __launch_bounds__(256) k_embed(const int* __restrict__ tgt,
                                               const float* __restrict__ et) {
    int idx = blockIdx.x*256 + threadIdx.x;          // < TS*B*H
    int e = idx & (H - 1);
    int r = idx >> 9;
    int tok = tgt[r];
    (&g_emb[0][0])[idx] = et[(size_t)tok*H + e];
}

// Pack Wgen into per-lane mma A-fragment order (hi/lo bf16 split).
__global__ void __launch_bounds__(256) k_pack(const float* __restrict__ Wgen) {
    int idx = blockIdx.x*256 + threadIdx.x;          // < NG*KC*32*8
    int reg  = idx & 7;
    int lane = (idx >> 3) & 31;
    int c    = (idx >> 8) & 31;
    int g    = idx >> 13;
    int split = reg >> 2, r4 = reg & 3;
    int gid = lane >> 2, tig = lane & 3;
    int n = g*16 + gid + ((r4 & 1) ? 8 : 0);
    int k = c*16 + tig*2 + ((r4 & 2) ? 8 : 0);
    float w0 = Wgen[(size_t)n*H + k];
    float w1 = Wgen[(size_t)n*H + k + 1];
    float h0 = bf16_hi_f(w0), h1 = bf16_hi_f(w1);
    g_Wq[idx] = (split == 0) ? pack_bf16(h0, h1) : pack_bf16(w0 - h0, w1 - h1);
}

// Merged: generator(t-1) blocks [0, GENB) + 4 gate GEMVs for step t.
__global__ void __launch_bounds__(256) k_mix(const float* __restrict__ Wx0,
                                             const float* __restrict__ Wh0,
                                             const float* __restrict__ Wh1,
                                             const float* __restrict__ bgen,
                                             float* __restrict__ out,
                                             int t, int tGen) {
    __shared__ MixSmem u;
    if ((int)blockIdx.x < GENB) {
        if (tGen >= 0) gen_tile(blockIdx.x, tGen, bgen, out, u.Dsm);
        return;
    }
    const int blk = blockIdx.x - GENB;                // 0..1023
    const int p = blk >> 8, nb = blk & 255;
    const int warp = threadIdx.x >> 5, lane = threadIdx.x & 31;
    const int n = nb*8 + warp;                        // 0..2047
    const float* Wrow; const float* X; float* dst;
    if (p == 0)      { Wrow = Wx0 + (size_t)n*1024;        X = g_emb[t]; dst = &g_part0[0][0]; }
    else if (p == 1) { Wrow = Wx0 + (size_t)n*1024 + 512;  X = g_dec;    dst = &g_part0[1][0]; }
    else if (p == 2) { Wrow = Wh0 + (size_t)n*512;         X = g_h[0];   dst = &g_part0[2][0]; }
    else             { Wrow = Wh1 + (size_t)n*512;         X = g_h[1];   dst = &g_part1[1][0]; }
    float acc[B] = {};
    warp_gemv_acc(Wrow, X, acc);
    float s = warp_reduce_b(acc, u.gemv[warp]);
    dst[n*B + lane] = s;
}

// Wx1 x h0 (needs act0 output) -> part1[0]
__global__ void __launch_bounds__(256) k_g1p0(const float* __restrict__ Wx1) {
    __shared__ float sm[8][33*32];
    const int warp = threadIdx.x >> 5, lane = threadIdx.x & 31;
    const int n = blockIdx.x*8 + warp;
    float acc[B] = {};
    warp_gemv_acc(Wx1 + (size_t)n*512, g_h[0], acc);
    float s = warp_reduce_b(acc, sm[warp]);
    g_part1[0][n*B + lane] = s;
}

// Layer-0 activation (3 partials)
__global__ void __launch_bounds__(256) k_act0(const float* __restrict__ bias) {
    int idx = blockIdx.x*256 + threadIdx.x;
    int b = idx & 31, j = idx >> 5;
    float gi = bias[j], gf = bias[512+j], gg = bias[1024+j], go = bias[1536+j];
#pragma unroll
    for (int p = 0; p < 3; p++) {
        const float* pp = &g_part0[p][0];
        gi += pp[(j       )*B + b];
        gf += pp[(512 + j )*B + b];
        gg += pp[(1024 + j)*B + b];
        go += pp[(1536 + j)*B + b];
    }
    float c  = g_c[0][b*H + j];
    float cn = sigm(gf)*c + sigm(gi)*tanhf(gg);
    g_c[0][b*H + j] = cn;
    g_h[0][b*H + j] = sigm(go)*tanhf(cn);
}

// Fused: layer-1 activation + q projection + attention + context.
__global__ void __launch_bounds__(256) k_attn(const float* __restrict__ mb,
                                              const int* __restrict__ mlen,
                                              const float* __restrict__ b1v,
                                              float* __restrict__ attn_out, int t) {
    __shared__ float sh1[H];
    __shared__ float sq[H];
    __shared__ float al[S];
    __shared__ float red[256];
    const int b = blockIdx.x;
    const int tid = threadIdx.x, warp = tid >> 5, lane = tid & 31;
    const int len = mlen[b];

    for (int j = tid; j < H; j += 256) {
        float gi = b1v[j], gf = b1v[512+j], gg = b1v[1024+j], go = b1v[1536+j];
#pragma unroll
        for (int p = 0; p < 2; p++) {
            const float* pp = &g_part1[p][0];
            gi += pp[(j       )*B + b];
            gf += pp[(512 + j )*B + b];
            gg += pp[(1024 + j)*B + b];
            go += pp[(1536 + j)*B + b];
        }
        float c  = g_c[1][b*H + j];
        float cn = sigm(gf)*c + sigm(gi)*tanhf(gg);
        g_c[1][b*H + j] = cn;
        float hn = sigm(go)*tanhf(cn);
        g_h[1][b*H + j] = hn;
        sh1[j] = hn;
    }
    __syncthreads();

    for (int n0 = warp; n0 < H; n0 += 8) {
        const float* wr = g_WaT + (size_t)n0*H;
        float a = 0.f;
#pragma unroll
        for (int kk = 0; kk < 4; kk++) {
            int k = kk*128 + lane*4;
            float4 w  = *reinterpret_cast<const float4*>(wr + k);
            float4 hx = *reinterpret_cast<const float4*>(sh1 + k);
            a += w.x*hx.x + w.y*hx.y + w.z*hx.z + w.w*hx.w;
        }
#pragma unroll
        for (int off = 16; off; off >>= 1) a += __shfl_xor_sync(0xffffffffu, a, off);
        if (lane == 0) sq[n0] = a;
    }
    __syncthreads();

    for (int s0 = warp; s0 < S; s0 += 8) {
        const float* m = mb + ((size_t)s0*B + b)*H;
        float a = 0.f;
#pragma unroll
        for (int kk = 0; kk < 4; kk++) {
            int k = kk*128 + lane*4;
            float4 mv = *reinterpret_cast<const float4*>(m + k);
            float4 qv = *reinterpret_cast<const float4*>(sq + k);
            a += mv.x*qv.x + mv.y*qv.y + mv.z*qv.z + mv.w*qv.w;
        }
#pragma unroll
        for (int off = 16; off; off >>= 1) a += __shfl_xor_sync(0xffffffffu, a, off);
        if (lane == 0) al[s0] = (s0 < len) ? a : -1.0e9f;
    }
    __syncthreads();

    float v = al[tid];
    red[tid] = v; __syncthreads();
    for (int o = 128; o; o >>= 1) { if (tid < o) red[tid] = fmaxf(red[tid], red[tid+o]); __syncthreads(); }
    float vmax = red[0];
    __syncthreads();
    float e = expf(v - vmax);
    red[tid] = e; __syncthreads();
    for (int o = 128; o; o >>= 1) { if (tid < o) red[tid] += red[tid+o]; __syncthreads(); }
    float p = e / red[0];
    al[tid] = p;
    attn_out[((size_t)t*B + b)*S + tid] = p;
    __syncthreads();

    for (int k = tid; k < H; k += 256) {
        float acc = 0.f;
#pragma unroll 4
        for (int s = 0; s < S; s++) acc += al[s] * mb[((size_t)s*B + b)*H + k];
        g_ctx[b*H + k] = acc;
    }
}

// Wc projection + tanh; writes fp32 dec AND scatters B fragments (fused xpack).
__global__ void __launch_bounds__(256) k_wc(const float* __restrict__ Wc) {
    __shared__ float sm[8][33*32];
    const int warp = threadIdx.x >> 5, lane = threadIdx.x & 31;
    const int n = blockIdx.x*8 + warp;                // 0..511
    float acc[B] = {};
    warp_gemv_acc(Wc + (size_t)n*1024,       g_ctx,  acc);
    warp_gemv_acc(Wc + (size_t)n*1024 + 512, g_h[1], acc);
    float s = warp_reduce_b(acc, sm[warp]);
    float d = tanhf(s);
    g_dec[lane*H + n] = d;
    scatter_frag(g_xq, lane, n, d);
}

// one pass at the end over all timesteps
__global__ void __launch_bounds__(256) k_lsm(float* __restrict__ out) {
    __shared__ float lz;
    const int t = blockIdx.z, b = blockIdx.y;
    if (threadIdx.x == 0) lz = logf(g_sumZ[t*B + b]);
    __syncthreads();
    int v = blockIdx.x*256 + threadIdx.x;
    out[((size_t)(t*B + b))*V + v] -= lz;
}

// ------------------------- launch -------------------------------------------
extern "C" void kernel_launch(void* const* d_in, const int* in_sizes, int n_in,
                              void* d_out, int out_size) {
    const int*   tgt   = (const int*)  d_in[0];
    const float* mb    = (const float*)d_in[1];
    const int*   mlen  = (const int*)  d_in[2];
    const float* enc_h = (const float*)d_in[3];
    const float* enc_c = (const float*)d_in[4];
    const float* emb   = (const float*)d_in[5];
    const float* Wx0   = (const float*)d_in[6];
    const float* Wh0   = (const float*)d_in[7];
    const float* b0    = (const float*)d_in[8];
    const float* Wx1   = (const float*)d_in[9];
    const float* Wh1   = (const float*)d_in[10];
    const float* b1    = (const float*)d_in[11];
    const float* Wa    = (const float*)d_in[12];
    const float* Wc    = (const float*)d_in[13];
    const float* Wgen  = (const float*)d_in[14];
    const float* bgen  = (const float*)d_in[15];

    float* out      = (float*)d_out;
    float* attn_out = out + (size_t)TS*B*V;

    k_init <<<(H*H + 255)/256, 256>>>(enc_h, enc_c, Wa);
    k_embed<<<(TS*B*H)/256, 256>>>(tgt, emb);
    k_pack <<<NG*32, 256>>>(Wgen);

    for (int t = 0; t < TS; t++) {
        // generator(t-1) overlapped with step-t gate GEMVs in one launch
        k_mix  <<<GENB + 4*(G4/8), 256>>>(Wx0, Wh0, Wh1, bgen, out, t, t - 1);
        k_act0 <<<(B*H)/256, 256>>>(b0);
        k_g1p0 <<<G4/8, 256>>>(Wx1);
        k_attn <<<B, 256>>>(mb, mlen, b1, attn_out, t);
        k_wc   <<<H/8, 256>>>(Wc);
    }
    // final generator (t = TS-1): gen blocks only
    k_mix<<<GENB, 256>>>(Wx0, Wh0, Wh1, bgen, out, 0, TS - 1);
    k_lsm<<<dim3(V/256, B, TS), 256>>>(out);
}